// round 16
// baseline (speedup 1.0000x reference)
#include <cuda_runtime.h>
#include <cuda_bf16.h>
#include <cstdint>

#define B_N 262144
#define C_N 256
#define D_N 64
#define O_N 8
#define NTILES 2048          // B_N / 128
#define NCTA 296             // 2 per SM, persistent
#define THREADS 128          // 4 warps, 32 rows each

// ---- shared memory byte offsets ----
#define OFF_CHI 0            // centers hi bf16 (ldmatrix swizzled)  32768
#define OFF_CH8 32768        // centers e4m3, byte-permuted          16384
#define OFF_CL8 49152        // centers residual*256 e4m3            16384
#define OFF_XHI 65536        // x hi bf16 (ldmatrix swizzled)        16384
#define OFF_XH8 81920        // x e4m3, byte-permuted                 8192
#define OFF_XL8 90112        // x residual*256 e4m3                   8192
#define OFF_SK  98304        // 256 x float2 (s2, k2)                 2048
#define OFF_RW  100352       // permuted [nb][k][lq] 16B chunks       8192
#define OFF_XSQ 108544       // 128 f32                                512
#define SMEM_BYTES 109056

typedef unsigned long long ull;

static __device__ __forceinline__ uint32_t smem_u32(const void* p) {
    uint32_t a;
    asm("{ .reg .u64 t; cvta.to.shared.u64 t, %1; cvt.u32.u64 %0, t; }"
        : "=r"(a) : "l"(p));
    return a;
}
static __device__ __forceinline__ float ex2f(float x) {
    float r; asm("ex2.approx.f32 %0, %1;" : "=f"(r) : "f"(x)); return r;
}
static __device__ __forceinline__ ull ffma2(ull a, ull b, ull c) {
    ull d; asm("fma.rn.f32x2 %0, %1, %2, %3;" : "=l"(d) : "l"(a), "l"(b), "l"(c));
    return d;
}
static __device__ __forceinline__ float2 unpack2(ull v) {
    float2 r; asm("mov.b64 {%0, %1}, %2;" : "=f"(r.x), "=f"(r.y) : "l"(v)); return r;
}
static __device__ __forceinline__ ull pack2(float a) {
    ull r; asm("mov.b64 %0, {%1, %2};" : "=l"(r) : "f"(a), "f"(a)); return r;
}

// swizzled byte address of a 16B granule: row stride 128B, XOR swizzle on quads
static __device__ __forceinline__ uint32_t swz(uint32_t base, int row, int kb) {
    return base + row * 128 + (kb ^ ((row & 7) << 4));
}

static __device__ __forceinline__ void ldsm4(uint32_t& r0, uint32_t& r1,
                                             uint32_t& r2, uint32_t& r3,
                                             uint32_t a) {
    asm volatile("ldmatrix.sync.aligned.m8n8.x4.shared.b16 {%0,%1,%2,%3}, [%4];"
                 : "=r"(r0), "=r"(r1), "=r"(r2), "=r"(r3) : "r"(a));
}

static __device__ __forceinline__ void mma16816(float* d, const uint32_t* a,
                                                uint32_t b0, uint32_t b1) {
    asm volatile(
        "mma.sync.aligned.m16n8k16.row.col.f32.bf16.bf16.f32 "
        "{%0,%1,%2,%3}, {%4,%5,%6,%7}, {%8,%9}, {%0,%1,%2,%3};"
        : "+f"(d[0]), "+f"(d[1]), "+f"(d[2]), "+f"(d[3])
        : "r"(a[0]), "r"(a[1]), "r"(a[2]), "r"(a[3]), "r"(b0), "r"(b1));
}

static __device__ __forceinline__ void mma_e4m3(float* d, const uint32_t* a,
                                                uint32_t b0, uint32_t b1) {
    asm volatile(
        "mma.sync.aligned.m16n8k32.row.col.f32.e4m3.e4m3.f32 "
        "{%0,%1,%2,%3}, {%4,%5,%6,%7}, {%8,%9}, {%0,%1,%2,%3};"
        : "+f"(d[0]), "+f"(d[1]), "+f"(d[2]), "+f"(d[3])
        : "r"(a[0]), "r"(a[1]), "r"(a[2]), "r"(a[3]), "r"(b0), "r"(b1));
}

// pack 4 floats into 4 e4m3 bytes (byte0 = a, ascending k order)
static __device__ __forceinline__ uint32_t f4_e4m3(float a, float b, float c, float d) {
    uint16_t lo, hi;
    asm("cvt.rn.satfinite.e4m3x2.f32 %0, %1, %2;" : "=h"(lo) : "f"(b), "f"(a));
    asm("cvt.rn.satfinite.e4m3x2.f32 %0, %1, %2;" : "=h"(hi) : "f"(d), "f"(c));
    return (uint32_t)lo | ((uint32_t)hi << 16);
}

// stage one float4 (quad d4 of a 64-float row): bf16-hi (swizzled) + e4m3 hi/lo
static __device__ __forceinline__ void stage_all(char* smemc, uint32_t hibase,
                                                 uint32_t h8base, uint32_t l8base,
                                                 int row, int d4, float4 v) {
    __nv_bfloat16 b0 = __float2bfloat16_rn(v.x);
    __nv_bfloat16 b1 = __float2bfloat16_rn(v.y);
    __nv_bfloat16 b2 = __float2bfloat16_rn(v.z);
    __nv_bfloat16 b3 = __float2bfloat16_rn(v.w);
    __nv_bfloat162 p01; p01.x = b0; p01.y = b1;
    __nv_bfloat162 p23; p23.x = b2; p23.y = b3;
    int off = row * 128 + (((d4 >> 1) * 16) ^ ((row & 7) << 4)) + (d4 & 1) * 8;
    *reinterpret_cast<uint2*>(smemc + hibase + off) =
        make_uint2(*reinterpret_cast<uint32_t*>(&p01),
                   *reinterpret_cast<uint32_t*>(&p23));
    float lx = (v.x - __bfloat162float(b0)) * 256.f;
    float ly = (v.y - __bfloat162float(b1)) * 256.f;
    float lz = (v.z - __bfloat162float(b2)) * 256.f;
    float lw = (v.w - __bfloat162float(b3)) * 256.f;
    // permuted byte layout: k = 16t + 4q + j stored at row*64 + q*16 + t*4 + j
    int poff = row * 64 + (d4 & 3) * 16 + (d4 >> 2) * 4;
    *reinterpret_cast<uint32_t*>(smemc + h8base + poff) = f4_e4m3(v.x, v.y, v.z, v.w);
    *reinterpret_cast<uint32_t*>(smemc + l8base + poff) = f4_e4m3(lx, ly, lz, lw);
}

__global__ void __launch_bounds__(THREADS, 2)
fuzzy_mma(const float* __restrict__ x,
          const float* __restrict__ centers,
          const float* __restrict__ widths,
          const float* __restrict__ rw,
          float* __restrict__ out) {
    extern __shared__ __align__(1024) char smemc[];
    float* smf = reinterpret_cast<float*>(smemc);
    const uint32_t su = smem_u32(smemc);
    const int tid = threadIdx.x;
    const int wid = tid >> 5;
    const int lane = tid & 31;
    const int lq = lane & 3;
    const int bid = blockIdx.x;

    // ========== one-time: centers (bf16-hi + e4m3 hi/lo), sk, rw ==========
    {
        const float4* cg = reinterpret_cast<const float4*>(centers);
        const float LOG2E = 1.4426950408889634f;
#pragma unroll 4
        for (int i = 0; i < 32; i++) {
            int j = tid + i * THREADS;          // float4 index, 4096 total
            float4 v = cg[j];
            float p = v.x * v.x;
            p = fmaf(v.y, v.y, p);
            p = fmaf(v.z, v.z, p);
            p = fmaf(v.w, v.w, p);
            p += __shfl_xor_sync(0xffffffffu, p, 1);
            p += __shfl_xor_sync(0xffffffffu, p, 2);
            p += __shfl_xor_sync(0xffffffffu, p, 4);
            p += __shfl_xor_sync(0xffffffffu, p, 8);
            stage_all(smemc, OFF_CHI, OFF_CH8, OFF_CL8, j >> 4, j & 15, v);
            if ((tid & 15) == 0) {
                int row = j >> 4;
                float w = widths[row];
                float s = LOG2E / (2.f * w * w);
                smf[OFF_SK / 4 + 2 * row] = s;
                smf[OFF_SK / 4 + 2 * row + 1] = -p * s;
            }
        }
        // rw permuted: new[nb*16 + k*4 + lq] = orig[nb*16 + lq*4 + k]
        const float4* rg = reinterpret_cast<const float4*>(rw);
        float4* rs = reinterpret_cast<float4*>(smemc + OFF_RW);
#pragma unroll
        for (int i = 0; i < 4; i++) {
            int n = tid + i * THREADS;
            int orig = (n & ~15) | ((n & 3) << 2) | ((n >> 2) & 3);
            rs[n] = rg[orig];
        }
    }
    __syncthreads();

    // ldmatrix lane address components (constant per thread)
    const int la_row = ((lane >> 3) & 1) * 8 + (lane & 7);   // A: row within 16
    const int la_k16 = (lane >> 4);                          // A: +16B for k+8
    const int lb_row = lane & 7;                             // B: n within 8
    const int lb_k16 = (lane >> 3);                          // B: granule 0..3
    const int lr = lane >> 2;                                // fp8 row within 8
    const int m0 = wid * 32;

    // ================= persistent tile loop =================
    for (int tile = bid; tile < NTILES; tile += NCTA) {
        // ---- stage x tile: coalesced read + shfl xsq + hi/lo stores ----
        {
            const float4* xg = reinterpret_cast<const float4*>(x) + (size_t)tile * 2048;
#pragma unroll 4
            for (int i = 0; i < 16; i++) {
                int j = tid + i * THREADS;
                float4 v = xg[j];
                float p = v.x * v.x;
                p = fmaf(v.y, v.y, p);
                p = fmaf(v.z, v.z, p);
                p = fmaf(v.w, v.w, p);
                p += __shfl_xor_sync(0xffffffffu, p, 1);
                p += __shfl_xor_sync(0xffffffffu, p, 2);
                p += __shfl_xor_sync(0xffffffffu, p, 4);
                p += __shfl_xor_sync(0xffffffffu, p, 8);
                stage_all(smemc, OFF_XHI, OFF_XH8, OFF_XL8, j >> 4, j & 15, v);
                if ((tid & 15) == 0) smf[OFF_XSQ / 4 + (j >> 4)] = p;
            }
        }
        __syncthreads();

        // ---- A fragments: bf16 hi via ldmatrix (2 groups of 16 rows) ----
        uint32_t ah0[16], ah1[16];
#pragma unroll
        for (int s = 0; s < 4; s++) {
            int r0 = m0 + la_row;
            int r1 = r0 + 16;
            int kb = s * 32 + la_k16 * 16;
            ldsm4(ah0[4 * s], ah0[4 * s + 1], ah0[4 * s + 2], ah0[4 * s + 3],
                  swz(su + OFF_XHI, r0, kb));
            ldsm4(ah1[4 * s], ah1[4 * s + 1], ah1[4 * s + 2], ah1[4 * s + 3],
                  swz(su + OFF_XHI, r1, kb));
        }
        // ---- A fragments: e4m3 hi/lo via direct conflict-free LDS.128 ----
        // lane addr = row*64 + (lane&3)*16; uint4 words w[t] = bytes k=16t+4q..+3
        // k32 frag ks: a0=r0.w[2ks], a1=r1.w[2ks], a2=r0.w[2ks+1], a3=r1.w[2ks+1]
        uint32_t a8h0[8], a8h1[8], a8l0[8], a8l1[8];
        {
            const int lb16 = (lane & 3) * 16;
#define LD8(base, row) (*reinterpret_cast<const uint4*>(smemc + (base) + (row) * 64 + lb16))
#define FRAG8(dst, ra, rb)                                                   \
            { uint4 _a = (ra), _b = (rb);                                    \
              dst[0] = _a.x; dst[1] = _b.x; dst[2] = _a.y; dst[3] = _b.y;    \
              dst[4] = _a.z; dst[5] = _b.z; dst[6] = _a.w; dst[7] = _b.w; }
            FRAG8(a8h0, LD8(OFF_XH8, m0 + lr), LD8(OFF_XH8, m0 + lr + 8))
            FRAG8(a8h1, LD8(OFF_XH8, m0 + lr + 16), LD8(OFF_XH8, m0 + lr + 24))
            FRAG8(a8l0, LD8(OFF_XL8, m0 + lr), LD8(OFF_XL8, m0 + lr + 8))
            FRAG8(a8l1, LD8(OFF_XL8, m0 + lr + 16), LD8(OFF_XL8, m0 + lr + 24))
#undef FRAG8
#undef LD8
        }
        float xs0 = smf[OFF_XSQ / 4 + m0 + lr];
        float xs1 = smf[OFF_XSQ / 4 + m0 + lr + 8];
        float xs2 = smf[OFF_XSQ / 4 + m0 + lr + 16];
        float xs3 = smf[OFF_XSQ / 4 + m0 + lr + 24];

        float den0 = 0.f, den1 = 0.f, den2 = 0.f, den3 = 0.f;
        ull num0[4] = {0, 0, 0, 0};
        ull num1[4] = {0, 0, 0, 0};
        ull num2[4] = {0, 0, 0, 0};
        ull num3[4] = {0, 0, 0, 0};

        // ---- n-block loop over 256 clusters ----
#pragma unroll 2
        for (int nb = 0; nb < 32; nb++) {
            const int n0 = nb * 8;
            // B hi (bf16) via ldmatrix
            uint32_t bh[8];
#pragma unroll
            for (int p = 0; p < 2; p++) {
                int row = n0 + lb_row;
                int kb = p * 64 + lb_k16 * 16;
                ldsm4(bh[4 * p], bh[4 * p + 1], bh[4 * p + 2], bh[4 * p + 3],
                      swz(su + OFF_CHI, row, kb));
            }
            // B e4m3 hi/lo: one LDS.128 each (addr = base + n0*64 + lane*16)
            uint4 b8h = *reinterpret_cast<const uint4*>(
                smemc + OFF_CH8 + n0 * 64 + lane * 16);
            uint4 b8l = *reinterpret_cast<const uint4*>(
                smemc + OFF_CL8 + n0 * 64 + lane * 16);
            float4 skv = *reinterpret_cast<const float4*>(
                smemc + OFF_SK + n0 * 8 + lq * 16);
            const ulonglong2* wp = reinterpret_cast<const ulonglong2*>(
                smemc + OFF_RW + nb * 256 + lq * 16);
            ulonglong2 w0 = wp[0];
            ulonglong2 w1 = wp[4];
            ulonglong2 w2 = wp[8];
            ulonglong2 w3 = wp[12];

            // hh pass (bf16, f32 acc): 2 chains of 4
            float acc0[4] = {0.f, 0.f, 0.f, 0.f};
            float acc1[4] = {0.f, 0.f, 0.f, 0.f};
#pragma unroll
            for (int s = 0; s < 4; s++) {
                int bi = (s >> 1) * 4 + (s & 1) * 2;
                mma16816(acc0, &ah0[4 * s], bh[bi], bh[bi + 1]);
                mma16816(acc1, &ah1[4 * s], bh[bi], bh[bi + 1]);
            }
            // residual passes (e4m3 k32): hl + lh into one acc, 2 chains of 4
            float r0a[4] = {0.f, 0.f, 0.f, 0.f};
            float r1a[4] = {0.f, 0.f, 0.f, 0.f};
            mma_e4m3(r0a, &a8h0[0], b8l.x, b8l.y);   // xh * cl  ks0
            mma_e4m3(r1a, &a8h1[0], b8l.x, b8l.y);
            mma_e4m3(r0a, &a8h0[4], b8l.z, b8l.w);   // ks1
            mma_e4m3(r1a, &a8h1[4], b8l.z, b8l.w);
            mma_e4m3(r0a, &a8l0[0], b8h.x, b8h.y);   // xl * ch  ks0
            mma_e4m3(r1a, &a8l1[0], b8h.x, b8h.y);
            mma_e4m3(r0a, &a8l0[4], b8h.z, b8h.w);   // ks1
            mma_e4m3(r1a, &a8l1[4], b8h.z, b8h.w);

            const float CR = 0.0078125f;   // 2*(1/256) folded: see t below
            // epilogue g0: cross = acc + r/256 ; t = 2*cross - xs
            {
                float t00 = fmaf(acc0[0], 2.f, fmaf(r0a[0], CR, -xs0));
                float t01 = fmaf(acc0[1], 2.f, fmaf(r0a[1], CR, -xs0));
                float t10 = fmaf(acc0[2], 2.f, fmaf(r0a[2], CR, -xs1));
                float t11 = fmaf(acc0[3], 2.f, fmaf(r0a[3], CR, -xs1));
                float m00 = ex2f(fmaf(skv.x, t00, skv.y));
                float m01 = ex2f(fmaf(skv.z, t01, skv.w));
                float m10 = ex2f(fmaf(skv.x, t10, skv.y));
                float m11 = ex2f(fmaf(skv.z, t11, skv.w));
                den0 += m00 + m01;
                den1 += m10 + m11;
                ull mA0 = pack2(m00), mB0 = pack2(m01);
                ull mA1 = pack2(m10), mB1 = pack2(m11);
                num0[0] = ffma2(mA0, w0.x, num0[0]);
                num0[1] = ffma2(mA0, w0.y, num0[1]);
                num0[2] = ffma2(mA0, w1.x, num0[2]);
                num0[3] = ffma2(mA0, w1.y, num0[3]);
                num0[0] = ffma2(mB0, w2.x, num0[0]);
                num0[1] = ffma2(mB0, w2.y, num0[1]);
                num0[2] = ffma2(mB0, w3.x, num0[2]);
                num0[3] = ffma2(mB0, w3.y, num0[3]);
                num1[0] = ffma2(mA1, w0.x, num1[0]);
                num1[1] = ffma2(mA1, w0.y, num1[1]);
                num1[2] = ffma2(mA1, w1.x, num1[2]);
                num1[3] = ffma2(mA1, w1.y, num1[3]);
                num1[0] = ffma2(mB1, w2.x, num1[0]);
                num1[1] = ffma2(mB1, w2.y, num1[1]);
                num1[2] = ffma2(mB1, w3.x, num1[2]);
                num1[3] = ffma2(mB1, w3.y, num1[3]);
            }
            // epilogue g1
            {
                float t00 = fmaf(acc1[0], 2.f, fmaf(r1a[0], CR, -xs2));
                float t01 = fmaf(acc1[1], 2.f, fmaf(r1a[1], CR, -xs2));
                float t10 = fmaf(acc1[2], 2.f, fmaf(r1a[2], CR, -xs3));
                float t11 = fmaf(acc1[3], 2.f, fmaf(r1a[3], CR, -xs3));
                float m00 = ex2f(fmaf(skv.x, t00, skv.y));
                float m01 = ex2f(fmaf(skv.z, t01, skv.w));
                float m10 = ex2f(fmaf(skv.x, t10, skv.y));
                float m11 = ex2f(fmaf(skv.z, t11, skv.w));
                den2 += m00 + m01;
                den3 += m10 + m11;
                ull mA0 = pack2(m00), mB0 = pack2(m01);
                ull mA1 = pack2(m10), mB1 = pack2(m11);
                num2[0] = ffma2(mA0, w0.x, num2[0]);
                num2[1] = ffma2(mA0, w0.y, num2[1]);
                num2[2] = ffma2(mA0, w1.x, num2[2]);
                num2[3] = ffma2(mA0, w1.y, num2[3]);
                num2[0] = ffma2(mB0, w2.x, num2[0]);
                num2[1] = ffma2(mB0, w2.y, num2[1]);
                num2[2] = ffma2(mB0, w3.x, num2[2]);
                num2[3] = ffma2(mB0, w3.y, num2[3]);
                num3[0] = ffma2(mA1, w0.x, num3[0]);
                num3[1] = ffma2(mA1, w0.y, num3[1]);
                num3[2] = ffma2(mA1, w1.x, num3[2]);
                num3[3] = ffma2(mA1, w1.y, num3[3]);
                num3[0] = ffma2(mB1, w2.x, num3[0]);
                num3[1] = ffma2(mB1, w2.y, num3[1]);
                num3[2] = ffma2(mB1, w3.x, num3[2]);
                num3[3] = ffma2(mB1, w3.y, num3[3]);
            }
        }

        // ---- quad reduction (lane bits 0..1) ----
#pragma unroll
        for (int s = 1; s < 4; s <<= 1) {
            den0 += __shfl_xor_sync(0xffffffffu, den0, s);
            den1 += __shfl_xor_sync(0xffffffffu, den1, s);
            den2 += __shfl_xor_sync(0xffffffffu, den2, s);
            den3 += __shfl_xor_sync(0xffffffffu, den3, s);
#pragma unroll
            for (int k = 0; k < 4; k++) {
                float2 u;
                u = unpack2(num0[k]);
                u.x += __shfl_xor_sync(0xffffffffu, u.x, s);
                u.y += __shfl_xor_sync(0xffffffffu, u.y, s);
                asm("mov.b64 %0, {%1, %2};" : "=l"(num0[k]) : "f"(u.x), "f"(u.y));
                u = unpack2(num1[k]);
                u.x += __shfl_xor_sync(0xffffffffu, u.x, s);
                u.y += __shfl_xor_sync(0xffffffffu, u.y, s);
                asm("mov.b64 %0, {%1, %2};" : "=l"(num1[k]) : "f"(u.x), "f"(u.y));
                u = unpack2(num2[k]);
                u.x += __shfl_xor_sync(0xffffffffu, u.x, s);
                u.y += __shfl_xor_sync(0xffffffffu, u.y, s);
                asm("mov.b64 %0, {%1, %2};" : "=l"(num2[k]) : "f"(u.x), "f"(u.y));
                u = unpack2(num3[k]);
                u.x += __shfl_xor_sync(0xffffffffu, u.x, s);
                u.y += __shfl_xor_sync(0xffffffffu, u.y, s);
                asm("mov.b64 %0, {%1, %2};" : "=l"(num3[k]) : "f"(u.x), "f"(u.y));
            }
        }

        if ((lane & 3) == 0) {
            size_t gr = (size_t)tile * 128 + m0 + lr;
            float inv;
            float2 u;
            float4 o;
            float4* go;
#define WRITE_ROWS(numA, denA, roff)                                        \
            inv = 1.0f / (denA);                                            \
            go = reinterpret_cast<float4*>(out + (gr + (roff)) * O_N);      \
            u = unpack2(numA[0]); o.x = u.x * inv; o.y = u.y * inv;         \
            u = unpack2(numA[1]); o.z = u.x * inv; o.w = u.y * inv;         \
            go[0] = o;                                                      \
            u = unpack2(numA[2]); o.x = u.x * inv; o.y = u.y * inv;         \
            u = unpack2(numA[3]); o.z = u.x * inv; o.w = u.y * inv;         \
            go[1] = o;
            WRITE_ROWS(num0, den0, 0)
            WRITE_ROWS(num1, den1, 8)
            WRITE_ROWS(num2, den2, 16)
            WRITE_ROWS(num3, den3, 24)
#undef WRITE_ROWS
        }
        __syncthreads();   // protect x tile before next stage
    }
}

extern "C" void kernel_launch(void* const* d_in, const int* in_sizes, int n_in,
                              void* d_out, int out_size) {
    const float* x       = (const float*)d_in[0];
    const float* centers = (const float*)d_in[1];
    const float* widths  = (const float*)d_in[2];
    const float* rw      = (const float*)d_in[3];
    float* out = (float*)d_out;

    cudaFuncSetAttribute(fuzzy_mma,
                         cudaFuncAttributeMaxDynamicSharedMemorySize, SMEM_BYTES);
    fuzzy_mma<<<NCTA, THREADS, SMEM_BYTES>>>(x, centers, widths, rw, out);
}

// round 17
// speedup vs baseline: 1.6889x; 1.6889x over previous
#include <cuda_runtime.h>
#include <cuda_fp16.h>
#include <cstdint>

#define B_N 262144
#define C_N 256
#define D_N 64
#define O_N 8
#define NTILES 2048          // B_N / 128
#define NCTA 444             // 3 per SM, persistent
#define THREADS 128          // 4 warps, 32 rows each

// ---- shared memory byte offsets ----
#define OFF_CH  0            // centers fp16 (ldmatrix swizzled): 256x128B  32768
#define OFF_XH  32768        // x fp16 (ldmatrix swizzled): 128x128B       16384
#define OFF_SK  49152        // 256 x float2 (s2, k2)                       2048
#define OFF_RW  51200        // permuted [nb][k][lq] 16B chunks             8192
#define OFF_XSQ 59392        // 128 f32                                      512
#define SMEM_BYTES 59904

typedef unsigned long long ull;

static __device__ __forceinline__ uint32_t smem_u32(const void* p) {
    uint32_t a;
    asm("{ .reg .u64 t; cvta.to.shared.u64 t, %1; cvt.u32.u64 %0, t; }"
        : "=r"(a) : "l"(p));
    return a;
}
static __device__ __forceinline__ float ex2f(float x) {
    float r; asm("ex2.approx.f32 %0, %1;" : "=f"(r) : "f"(x)); return r;
}
static __device__ __forceinline__ ull ffma2(ull a, ull b, ull c) {
    ull d; asm("fma.rn.f32x2 %0, %1, %2, %3;" : "=l"(d) : "l"(a), "l"(b), "l"(c));
    return d;
}
static __device__ __forceinline__ float2 unpack2(ull v) {
    float2 r; asm("mov.b64 {%0, %1}, %2;" : "=f"(r.x), "=f"(r.y) : "l"(v)); return r;
}
static __device__ __forceinline__ ull pack2(float a) {
    ull r; asm("mov.b64 %0, {%1, %2};" : "=l"(r) : "f"(a), "f"(a)); return r;
}

// swizzled byte address of a 16B granule: row stride 128B, XOR swizzle on quads
static __device__ __forceinline__ uint32_t swz(uint32_t base, int row, int kb) {
    return base + row * 128 + (kb ^ ((row & 7) << 4));
}

static __device__ __forceinline__ void ldsm4(uint32_t& r0, uint32_t& r1,
                                             uint32_t& r2, uint32_t& r3,
                                             uint32_t a) {
    asm volatile("ldmatrix.sync.aligned.m8n8.x4.shared.b16 {%0,%1,%2,%3}, [%4];"
                 : "=r"(r0), "=r"(r1), "=r"(r2), "=r"(r3) : "r"(a));
}

static __device__ __forceinline__ void mma16816(float* d, const uint32_t* a,
                                                uint32_t b0, uint32_t b1) {
    asm volatile(
        "mma.sync.aligned.m16n8k16.row.col.f32.f16.f16.f32 "
        "{%0,%1,%2,%3}, {%4,%5,%6,%7}, {%8,%9}, {%0,%1,%2,%3};"
        : "+f"(d[0]), "+f"(d[1]), "+f"(d[2]), "+f"(d[3])
        : "r"(a[0]), "r"(a[1]), "r"(a[2]), "r"(a[3]), "r"(b0), "r"(b1));
}

// stage one float4 (quad d4 of a 64-float row) as fp16, swizzled
static __device__ __forceinline__ void stage_f16(char* smemc, uint32_t base,
                                                 int row, int d4, float4 v) {
    __half2 p01 = __floats2half2_rn(v.x, v.y);
    __half2 p23 = __floats2half2_rn(v.z, v.w);
    int off = row * 128 + (((d4 >> 1) * 16) ^ ((row & 7) << 4)) + (d4 & 1) * 8;
    *reinterpret_cast<uint2*>(smemc + base + off) =
        make_uint2(*reinterpret_cast<uint32_t*>(&p01),
                   *reinterpret_cast<uint32_t*>(&p23));
}

__global__ void __launch_bounds__(THREADS, 3)
fuzzy_mma(const float* __restrict__ x,
          const float* __restrict__ centers,
          const float* __restrict__ widths,
          const float* __restrict__ rw,
          float* __restrict__ out) {
    extern __shared__ __align__(1024) char smemc[];
    float* smf = reinterpret_cast<float*>(smemc);
    const uint32_t su = smem_u32(smemc);
    const int tid = threadIdx.x;
    const int wid = tid >> 5;
    const int lane = tid & 31;
    const int lq = lane & 3;
    const int bid = blockIdx.x;

    // ========== one-time: centers -> fp16 (coalesced), sk, rw ==========
    {
        const float4* cg = reinterpret_cast<const float4*>(centers);
        const float LOG2E = 1.4426950408889634f;
#pragma unroll 4
        for (int i = 0; i < 32; i++) {
            int j = tid + i * THREADS;          // float4 index, 4096 total
            float4 v = cg[j];
            float p = v.x * v.x;
            p = fmaf(v.y, v.y, p);
            p = fmaf(v.z, v.z, p);
            p = fmaf(v.w, v.w, p);
            p += __shfl_xor_sync(0xffffffffu, p, 1);
            p += __shfl_xor_sync(0xffffffffu, p, 2);
            p += __shfl_xor_sync(0xffffffffu, p, 4);
            p += __shfl_xor_sync(0xffffffffu, p, 8);
            stage_f16(smemc, OFF_CH, j >> 4, j & 15, v);
            if ((tid & 15) == 0) {
                int row = j >> 4;
                float w = widths[row];
                float s = LOG2E / (2.f * w * w);
                smf[OFF_SK / 4 + 2 * row] = s;
                smf[OFF_SK / 4 + 2 * row + 1] = -p * s;
            }
        }
        // rw permuted: new[nb*16 + k*4 + lq] = orig[nb*16 + lq*4 + k]
        const float4* rg = reinterpret_cast<const float4*>(rw);
        float4* rs = reinterpret_cast<float4*>(smemc + OFF_RW);
#pragma unroll
        for (int i = 0; i < 4; i++) {
            int n = tid + i * THREADS;
            int orig = (n & ~15) | ((n & 3) << 2) | ((n >> 2) & 3);
            rs[n] = rg[orig];
        }
    }
    __syncthreads();

    // ldmatrix lane address components (constant per thread)
    const int la_row = ((lane >> 3) & 1) * 8 + (lane & 7);   // A: row within 16
    const int la_k16 = (lane >> 4);                          // A: +16B for k+8
    const int lb_row = lane & 7;                             // B: n within 8
    const int lb_k16 = (lane >> 3);                          // B: granule 0..3
    const int lr = lane >> 2;                                // acc row within 8
    const int m0 = wid * 32;

    // ================= persistent tile loop =================
    for (int tile = bid; tile < NTILES; tile += NCTA) {
        // ---- stage x tile: coalesced read + shfl xsq + fp16 store ----
        {
            const float4* xg = reinterpret_cast<const float4*>(x) + (size_t)tile * 2048;
#pragma unroll 4
            for (int i = 0; i < 16; i++) {
                int j = tid + i * THREADS;
                float4 v = xg[j];
                float p = v.x * v.x;
                p = fmaf(v.y, v.y, p);
                p = fmaf(v.z, v.z, p);
                p = fmaf(v.w, v.w, p);
                p += __shfl_xor_sync(0xffffffffu, p, 1);
                p += __shfl_xor_sync(0xffffffffu, p, 2);
                p += __shfl_xor_sync(0xffffffffu, p, 4);
                p += __shfl_xor_sync(0xffffffffu, p, 8);
                stage_f16(smemc, OFF_XH, j >> 4, j & 15, v);
                if ((tid & 15) == 0) smf[OFF_XSQ / 4 + (j >> 4)] = p;
            }
        }
        __syncthreads();

        // ---- A fragments: 32 rows per warp = two 16-row groups ----
        uint32_t ah0[16], ah1[16];
#pragma unroll
        for (int s = 0; s < 4; s++) {
            int r0 = m0 + la_row;
            int r1 = r0 + 16;
            int kb = s * 32 + la_k16 * 16;
            ldsm4(ah0[4 * s], ah0[4 * s + 1], ah0[4 * s + 2], ah0[4 * s + 3],
                  swz(su + OFF_XH, r0, kb));
            ldsm4(ah1[4 * s], ah1[4 * s + 1], ah1[4 * s + 2], ah1[4 * s + 3],
                  swz(su + OFF_XH, r1, kb));
        }
        float xs0 = smf[OFF_XSQ / 4 + m0 + lr];
        float xs1 = smf[OFF_XSQ / 4 + m0 + lr + 8];
        float xs2 = smf[OFF_XSQ / 4 + m0 + lr + 16];
        float xs3 = smf[OFF_XSQ / 4 + m0 + lr + 24];

        float den0 = 0.f, den1 = 0.f, den2 = 0.f, den3 = 0.f;
        ull num0[4] = {0, 0, 0, 0};
        ull num1[4] = {0, 0, 0, 0};
        ull num2[4] = {0, 0, 0, 0};
        ull num3[4] = {0, 0, 0, 0};

        // ---- n-block loop over 256 clusters ----
#pragma unroll 2
        for (int nb = 0; nb < 32; nb++) {
            const int n0 = nb * 8;
            uint32_t bh[8];
#pragma unroll
            for (int p = 0; p < 2; p++) {
                int row = n0 + lb_row;
                int kb = p * 64 + lb_k16 * 16;
                ldsm4(bh[4 * p], bh[4 * p + 1], bh[4 * p + 2], bh[4 * p + 3],
                      swz(su + OFF_CH, row, kb));
            }
            float4 skv = *reinterpret_cast<const float4*>(
                smemc + OFF_SK + n0 * 8 + lq * 16);
            const ulonglong2* wp = reinterpret_cast<const ulonglong2*>(
                smemc + OFF_RW + nb * 256 + lq * 16);
            ulonglong2 w0 = wp[0];
            ulonglong2 w1 = wp[4];
            ulonglong2 w2 = wp[8];
            ulonglong2 w3 = wp[12];

            // single-pass fp16 MMA: 2 independent chains of depth 4
            float acc0[4] = {0.f, 0.f, 0.f, 0.f};
            float acc1[4] = {0.f, 0.f, 0.f, 0.f};
#pragma unroll
            for (int s = 0; s < 4; s++) {
                int bi = (s >> 1) * 4 + (s & 1) * 2;
                mma16816(acc0, &ah0[4 * s], bh[bi], bh[bi + 1]);
                mma16816(acc1, &ah1[4 * s], bh[bi], bh[bi + 1]);
            }

            // epilogue g0 (rows m0+lr, m0+lr+8)
            {
                float m00 = ex2f(fmaf(skv.x, fmaf(acc0[0], 2.f, -xs0), skv.y));
                float m01 = ex2f(fmaf(skv.z, fmaf(acc0[1], 2.f, -xs0), skv.w));
                float m10 = ex2f(fmaf(skv.x, fmaf(acc0[2], 2.f, -xs1), skv.y));
                float m11 = ex2f(fmaf(skv.z, fmaf(acc0[3], 2.f, -xs1), skv.w));
                den0 += m00 + m01;
                den1 += m10 + m11;
                ull mA0 = pack2(m00), mB0 = pack2(m01);
                ull mA1 = pack2(m10), mB1 = pack2(m11);
                num0[0] = ffma2(mA0, w0.x, num0[0]);
                num0[1] = ffma2(mA0, w0.y, num0[1]);
                num0[2] = ffma2(mA0, w1.x, num0[2]);
                num0[3] = ffma2(mA0, w1.y, num0[3]);
                num0[0] = ffma2(mB0, w2.x, num0[0]);
                num0[1] = ffma2(mB0, w2.y, num0[1]);
                num0[2] = ffma2(mB0, w3.x, num0[2]);
                num0[3] = ffma2(mB0, w3.y, num0[3]);
                num1[0] = ffma2(mA1, w0.x, num1[0]);
                num1[1] = ffma2(mA1, w0.y, num1[1]);
                num1[2] = ffma2(mA1, w1.x, num1[2]);
                num1[3] = ffma2(mA1, w1.y, num1[3]);
                num1[0] = ffma2(mB1, w2.x, num1[0]);
                num1[1] = ffma2(mB1, w2.y, num1[1]);
                num1[2] = ffma2(mB1, w3.x, num1[2]);
                num1[3] = ffma2(mB1, w3.y, num1[3]);
            }
            // epilogue g1 (rows m0+lr+16, m0+lr+24)
            {
                float m00 = ex2f(fmaf(skv.x, fmaf(acc1[0], 2.f, -xs2), skv.y));
                float m01 = ex2f(fmaf(skv.z, fmaf(acc1[1], 2.f, -xs2), skv.w));
                float m10 = ex2f(fmaf(skv.x, fmaf(acc1[2], 2.f, -xs3), skv.y));
                float m11 = ex2f(fmaf(skv.z, fmaf(acc1[3], 2.f, -xs3), skv.w));
                den2 += m00 + m01;
                den3 += m10 + m11;
                ull mA0 = pack2(m00), mB0 = pack2(m01);
                ull mA1 = pack2(m10), mB1 = pack2(m11);
                num2[0] = ffma2(mA0, w0.x, num2[0]);
                num2[1] = ffma2(mA0, w0.y, num2[1]);
                num2[2] = ffma2(mA0, w1.x, num2[2]);
                num2[3] = ffma2(mA0, w1.y, num2[3]);
                num2[0] = ffma2(mB0, w2.x, num2[0]);
                num2[1] = ffma2(mB0, w2.y, num2[1]);
                num2[2] = ffma2(mB0, w3.x, num2[2]);
                num2[3] = ffma2(mB0, w3.y, num2[3]);
                num3[0] = ffma2(mA1, w0.x, num3[0]);
                num3[1] = ffma2(mA1, w0.y, num3[1]);
                num3[2] = ffma2(mA1, w1.x, num3[2]);
                num3[3] = ffma2(mA1, w1.y, num3[3]);
                num3[0] = ffma2(mB1, w2.x, num3[0]);
                num3[1] = ffma2(mB1, w2.y, num3[1]);
                num3[2] = ffma2(mB1, w3.x, num3[2]);
                num3[3] = ffma2(mB1, w3.y, num3[3]);
            }
        }

        // ---- quad reduction (lane bits 0..1) ----
#pragma unroll
        for (int s = 1; s < 4; s <<= 1) {
            den0 += __shfl_xor_sync(0xffffffffu, den0, s);
            den1 += __shfl_xor_sync(0xffffffffu, den1, s);
            den2 += __shfl_xor_sync(0xffffffffu, den2, s);
            den3 += __shfl_xor_sync(0xffffffffu, den3, s);
#pragma unroll
            for (int k = 0; k < 4; k++) {
                float2 u;
                u = unpack2(num0[k]);
                u.x += __shfl_xor_sync(0xffffffffu, u.x, s);
                u.y += __shfl_xor_sync(0xffffffffu, u.y, s);
                asm("mov.b64 %0, {%1, %2};" : "=l"(num0[k]) : "f"(u.x), "f"(u.y));
                u = unpack2(num1[k]);
                u.x += __shfl_xor_sync(0xffffffffu, u.x, s);
                u.y += __shfl_xor_sync(0xffffffffu, u.y, s);
                asm("mov.b64 %0, {%1, %2};" : "=l"(num1[k]) : "f"(u.x), "f"(u.y));
                u = unpack2(num2[k]);
                u.x += __shfl_xor_sync(0xffffffffu, u.x, s);
                u.y += __shfl_xor_sync(0xffffffffu, u.y, s);
                asm("mov.b64 %0, {%1, %2};" : "=l"(num2[k]) : "f"(u.x), "f"(u.y));
                u = unpack2(num3[k]);
                u.x += __shfl_xor_sync(0xffffffffu, u.x, s);
                u.y += __shfl_xor_sync(0xffffffffu, u.y, s);
                asm("mov.b64 %0, {%1, %2};" : "=l"(num3[k]) : "f"(u.x), "f"(u.y));
            }
        }

        if ((lane & 3) == 0) {
            size_t gr = (size_t)tile * 128 + m0 + lr;
            float inv;
            float2 u;
            float4 o;
            float4* go;
#define WRITE_ROWS(numA, denA, roff)                                        \
            inv = 1.0f / (denA);                                            \
            go = reinterpret_cast<float4*>(out + (gr + (roff)) * O_N);      \
            u = unpack2(numA[0]); o.x = u.x * inv; o.y = u.y * inv;         \
            u = unpack2(numA[1]); o.z = u.x * inv; o.w = u.y * inv;         \
            go[0] = o;                                                      \
            u = unpack2(numA[2]); o.x = u.x * inv; o.y = u.y * inv;         \
            u = unpack2(numA[3]); o.z = u.x * inv; o.w = u.y * inv;         \
            go[1] = o;
            WRITE_ROWS(num0, den0, 0)
            WRITE_ROWS(num1, den1, 8)
            WRITE_ROWS(num2, den2, 16)
            WRITE_ROWS(num3, den3, 24)
#undef WRITE_ROWS
        }
        __syncthreads();   // protect x tile before next stage
    }
}

extern "C" void kernel_launch(void* const* d_in, const int* in_sizes, int n_in,
                              void* d_out, int out_size) {
    const float* x       = (const float*)d_in[0];
    const float* centers = (const float*)d_in[1];
    const float* widths  = (const float*)d_in[2];
    const float* rw      = (const float*)d_in[3];
    float* out = (float*)d_out;

    cudaFuncSetAttribute(fuzzy_mma,
                         cudaFuncAttributeMaxDynamicSharedMemorySize, SMEM_BYTES);
    fuzzy_mma<<<NCTA, THREADS, SMEM_BYTES>>>(x, centers, widths, rw, out);
}